// round 13
// baseline (speedup 1.0000x reference)
#include <cuda_runtime.h>
#include <cuda_fp16.h>
#include <math.h>
#include <stdint.h>

// ---------------------------------------------------------------------------
// Problem constants
// ---------------------------------------------------------------------------
constexpr int B_    = 4;
constexpr int S_    = 1024;
constexpr int K_    = 1024;
constexpr int D_    = 1024;
constexpr int H_    = 16;
constexpr int HD_   = 64;
constexpr int COND_ = 1024;
constexpr int HID_  = 4096;          // MR * D
constexpr int MODD_ = 6 * D_;        // 6144
constexpr float EPS_    = 1e-5f;
constexpr float SCALE_  = 0.125f;    // 1/sqrt(64)
constexpr float GELU_C_ = 0.7978845608028654f;

// ---------------------------------------------------------------------------
// Scratch (device globals: no allocation allowed)
// ---------------------------------------------------------------------------
__device__ float    g_mod [B_ * MODD_];
__device__ __half   g_qn_h  [B_ * S_ * D_];
__device__ __half   g_kvn_h [B_ * K_ * D_];
__device__ float    g_q   [B_ * S_ * D_];
__device__ float    g_kv  [B_ * K_ * 2 * D_];
__device__ __half   g_attn_h[B_ * S_ * D_];
__device__ float    g_o   [B_ * S_ * D_];
__device__ float    g_x1  [B_ * S_ * D_];
__device__ __half   g_hn_h  [B_ * S_ * D_];
__device__ __half   g_h1_h  [B_ * S_ * HID_];
__device__ float    g_h2  [B_ * S_ * D_];
// K-major packed fp16 weights: word (n, kp) = {W[2kp][n], W[2kp+1][n]}
__device__ uint32_t g_wq_h [D_ * (D_ / 2)];
__device__ uint32_t g_wkv_h[2 * D_ * (D_ / 2)];
__device__ uint32_t g_wo_h [D_ * (D_ / 2)];
__device__ uint32_t g_w1_h [HID_ * (D_ / 2)];
__device__ uint32_t g_w2_h [D_ * (HID_ / 2)];

// ---------------------------------------------------------------------------
// helpers
// ---------------------------------------------------------------------------
__device__ __forceinline__ uint32_t smem_u32(const void* p)
{
    uint32_t a;
    asm("{ .reg .u64 t; cvta.to.shared.u64 t, %1; cvt.u32.u64 %0, t; }"
        : "=r"(a) : "l"(p));
    return a;
}

__device__ __forceinline__ void cpasync16(uint32_t smaddr, const void* g)
{
    asm volatile("cp.async.cg.shared.global [%0], [%1], 16;"
                 :: "r"(smaddr), "l"(g));
}

__device__ __forceinline__ float gelu_tanh_f(float x)
{
    const float x3 = x * x * x;
    const float t  = tanhf(GELU_C_ * (x + 0.044715f * x3));
    return 0.5f * x * (1.0f + t);
}

__device__ __forceinline__ float tf32r(float x)
{
    float r;
    asm("cvt.rna.tf32.f32 %0, %1;" : "=f"(r) : "f"(x));
    return r;
}

// tf32 m16n8k8 (attention only)
__device__ __forceinline__ void mma_tf32(float* d, const unsigned* a, const unsigned* b)
{
    asm volatile(
        "mma.sync.aligned.m16n8k8.row.col.f32.tf32.tf32.f32 "
        "{%0,%1,%2,%3}, {%4,%5,%6,%7}, {%8,%9}, {%0,%1,%2,%3};\n"
        : "+f"(d[0]), "+f"(d[1]), "+f"(d[2]), "+f"(d[3])
        : "r"(a[0]), "r"(a[1]), "r"(a[2]), "r"(a[3]),
          "r"(b[0]), "r"(b[1]));
}

// fp16 m16n8k16 (GEMMs), fp32 accumulate
__device__ __forceinline__ void mma_f16(float* d, const unsigned* a, const unsigned* b)
{
    asm volatile(
        "mma.sync.aligned.m16n8k16.row.col.f32.f16.f16.f32 "
        "{%0,%1,%2,%3}, {%4,%5,%6,%7}, {%8,%9}, {%0,%1,%2,%3};\n"
        : "+f"(d[0]), "+f"(d[1]), "+f"(d[2]), "+f"(d[3])
        : "r"(a[0]), "r"(a[1]), "r"(a[2]), "r"(a[3]),
          "r"(b[0]), "r"(b[1]));
}

#define LDSM_X4(r0, r1, r2, r3, addr) \
    asm volatile("ldmatrix.sync.aligned.m8n8.x4.shared.b16 {%0,%1,%2,%3}, [%4];" \
                 : "=r"(r0), "=r"(r1), "=r"(r2), "=r"(r3) : "r"(addr))

// ---------------------------------------------------------------------------
// Weight pack+transpose: W[K][N] fp32 -> Wt[n][kp] word = {W[2kp][n], W[2kp+1][n]}
// grid: (N/32, K/64). Coalesced read and write via smem transpose tile.
// ---------------------------------------------------------------------------
__global__ __launch_bounds__(256) void conv_wt_kernel(
    const float* __restrict__ W, uint32_t* __restrict__ out, int N, int Kd)
{
    __shared__ float tile[64][33];
    const int n0 = blockIdx.x * 32, k0 = blockIdx.y * 64;
    const int tid = threadIdx.x;
    for (int i = tid; i < 64 * 32; i += 256) {
        const int r = i >> 5, c = i & 31;
        tile[r][c] = W[(size_t)(k0 + r) * N + n0 + c];
    }
    __syncthreads();
    const int kw = Kd >> 1;
    for (int i = tid; i < 32 * 32; i += 256) {
        const int n = i >> 5, kp = i & 31;
        const __half2 h = __floats2half2_rn(tile[2 * kp][n], tile[2 * kp + 1][n]);
        out[(size_t)(n0 + n) * kw + (k0 >> 1) + kp] = *(const uint32_t*)&h;
    }
}

// ---------------------------------------------------------------------------
// mod = t_cond @ adaW + adab   -> g_mod [B, 6144]
// ---------------------------------------------------------------------------
__global__ __launch_bounds__(256) void mod_kernel(
    const float* __restrict__ t, const float* __restrict__ W,
    const float* __restrict__ bias)
{
    __shared__ float ts[B_ * COND_];          // 16 KB
    const int j = blockIdx.x * 256 + threadIdx.x;
    for (int i = threadIdx.x; i < B_ * COND_; i += 256) ts[i] = t[i];
    __syncthreads();

    float acc[B_];
    const float bz = bias[j];
#pragma unroll
    for (int b = 0; b < B_; ++b) acc[b] = bz;

    for (int c = 0; c < COND_; ++c) {
        const float w = W[(size_t)c * MODD_ + j];
#pragma unroll
        for (int b = 0; b < B_; ++b) acc[b] += ts[b * COND_ + c] * w;
    }
#pragma unroll
    for (int b = 0; b < B_; ++b) g_mod[b * MODD_ + j] = acc[b];
}

// ---------------------------------------------------------------------------
// LayerNorm (+ optional adaLN modulation) -> fp16 output (feeds GEMM A)
// ---------------------------------------------------------------------------
__global__ __launch_bounds__(256) void ln_kernel(
    const float* __restrict__ x, const float* __restrict__ w,
    __half* __restrict__ out, int shOff, int scOff, int useMod)
{
    const int row = blockIdx.x;
    const int b   = row >> 10;
    const int t   = threadIdx.x;
    const float4 v = *((const float4*)(x + (size_t)row * D_) + t);

    float sum = v.x + v.y + v.z + v.w;
    float sq  = v.x*v.x + v.y*v.y + v.z*v.z + v.w*v.w;
#pragma unroll
    for (int o = 16; o; o >>= 1) {
        sum += __shfl_xor_sync(~0u, sum, o);
        sq  += __shfl_xor_sync(~0u, sq,  o);
    }
    __shared__ float s1[8], s2[8], st[2];
    const int wid = t >> 5, lane = t & 31;
    if (lane == 0) { s1[wid] = sum; s2[wid] = sq; }
    __syncthreads();
    if (t == 0) {
        float a = 0.f, c = 0.f;
#pragma unroll
        for (int i = 0; i < 8; ++i) { a += s1[i]; c += s2[i]; }
        const float mean = a * (1.0f / D_);
        const float var  = c * (1.0f / D_) - mean * mean;
        st[0] = mean; st[1] = rsqrtf(var + EPS_);
    }
    __syncthreads();
    const float mean = st[0], rstd = st[1];
    const int d = t * 4;
    const float4 w4 = *(const float4*)(w + d);
    float4 y;
    y.x = (v.x - mean) * rstd * w4.x;
    y.y = (v.y - mean) * rstd * w4.y;
    y.z = (v.z - mean) * rstd * w4.z;
    y.w = (v.w - mean) * rstd * w4.w;
    if (useMod) {
        const float* mb = g_mod + b * MODD_;
        const float4 sh = *(const float4*)(mb + shOff + d);
        const float4 sc = *(const float4*)(mb + scOff + d);
        y.x = y.x * (1.f + sc.x) + sh.x;
        y.y = y.y * (1.f + sc.y) + sh.y;
        y.z = y.z * (1.f + sc.z) + sh.z;
        y.w = y.w * (1.f + sc.w) + sh.w;
    }
    uint2 u;
    __half2 h0 = __floats2half2_rn(y.x, y.y);
    __half2 h1 = __floats2half2_rn(y.z, y.w);
    u.x = *(const uint32_t*)&h0;
    u.y = *(const uint32_t*)&h1;
    *((uint2*)(out + (size_t)row * D_) + t) = u;
}

// ---------------------------------------------------------------------------
// fp16 mma GEMM v5: C[M,N] = A[M,K] @ B[K,N]
//   A: fp16 row-major [M][K]; B: K-major packed words Wt[n][kp].
//   128x128 tile, Ktile=32 halves, 3-stage cp.async, 8 warps (64x32),
//   m16n8k16, fp32 accum. Fragment loads via ldmatrix.x4 (12 LDSM/ktile
//   instead of 48 LDS). ASTR=BSTR=20-word padded rows: ldmatrix phases
//   hit 8 distinct 16B bank-groups (verified by enumeration).
// MODE: 0 = plain f32 out, 1 = +bias f32 out, 2 = gelu(+bias) fp16 out
// ---------------------------------------------------------------------------
constexpr int ASTR = 20;                     // words per staged row (16 + 4 pad)
constexpr int BSTR = 20;
constexpr int A_STAGE = 128 * ASTR;          // 2560 words
constexpr int B_STAGE = 128 * BSTR;          // 2560 words
constexpr int GEMM_SMEM_BYTES = (3 * A_STAGE + 3 * B_STAGE) * 4;   // 61440

template <int MODE>
__global__ __launch_bounds__(256, 2) void mma_gemm(
    const __half* __restrict__ A, const uint32_t* __restrict__ Bw,
    const float* __restrict__ bias, void* __restrict__ Cv,
    int M, int N, int Kd)
{
    extern __shared__ uint32_t dynw[];
    uint32_t* AsmW = dynw;                    // [3][A_STAGE]
    uint32_t* BsmW = dynw + 3 * A_STAGE;      // [3][B_STAGE]
    const uint32_t sA = smem_u32(AsmW);
    const uint32_t sB = smem_u32(BsmW);

    const int tid   = threadIdx.x;
    const int lane  = tid & 31, wid = tid >> 5;
    const int warpM = wid >> 2, warpN = wid & 3;     // 2 x 4 warps
    const int quad  = lane >> 2, q4 = lane & 3;

    // cp.async staging coords (identical geometry for A and B)
    const int sRow = tid >> 1;               // 0..127
    const int sHalf = tid & 1;               // which 8-word half of the 16-word row

    const int kw = Kd >> 1;                  // B row stride in words
    const __half*   Ag = A  + (size_t)(blockIdx.y * 128 + sRow) * Kd + sHalf * 16;
    const uint32_t* Bg = Bw + (size_t)(blockIdx.x * 128 + sRow) * kw + sHalf * 8;
    const uint32_t stOff = (uint32_t)(sRow * ASTR + sHalf * 8) * 4;

    // ldmatrix per-lane base offsets (bytes within a stage)
    const uint32_t aLaneOff =
        (uint32_t)((warpM * 64 + (lane & 15)) * ASTR + ((lane & 16) >> 2)) * 4;
    const uint32_t bLaneOff =
        (uint32_t)((warpN * 32 + (lane & 7) + ((lane & 16) >> 1)) * BSTR
                   + ((lane & 8) >> 1)) * 4;

    const int ktiles = Kd >> 5;              // 32 halves per tile

    auto issue = [&](int s) {
        const int slot = s % 3;
        const uint32_t da = sA + (uint32_t)slot * (A_STAGE * 4) + stOff;
        const __half* ag = Ag + (size_t)s * 32;
        cpasync16(da,      ag);
        cpasync16(da + 16, ag + 8);
        const uint32_t db = sB + (uint32_t)slot * (B_STAGE * 4) + stOff;
        const uint32_t* bg = Bg + (size_t)s * 16;
        cpasync16(db,      bg);
        cpasync16(db + 16, bg + 4);
    };

    float acc[16][4];
#pragma unroll
    for (int i = 0; i < 16; ++i)
#pragma unroll
        for (int j = 0; j < 4; ++j) acc[i][j] = 0.f;

    issue(0);
    asm volatile("cp.async.commit_group;" ::: "memory");
    issue(1);
    asm volatile("cp.async.commit_group;" ::: "memory");

    for (int kt = 0; kt < ktiles; ++kt) {
        asm volatile("cp.async.wait_group 1;" ::: "memory");
        __syncthreads();

        if (kt + 2 < ktiles) issue(kt + 2);
        asm volatile("cp.async.commit_group;" ::: "memory");

        const int slot = kt % 3;
        const uint32_t aBase = sA + (uint32_t)slot * (A_STAGE * 4) + aLaneOff;
        const uint32_t bBase = sB + (uint32_t)slot * (B_STAGE * 4) + bLaneOff;

#pragma unroll
        for (int kk = 0; kk < 2; ++kk) {     // two k16 steps per 32-half tile
            unsigned af[4][4], bf[4][2];
#pragma unroll
            for (int mi = 0; mi < 4; ++mi) {
                const uint32_t addr = aBase + (uint32_t)(mi * 16 * ASTR + kk * 8) * 4;
                LDSM_X4(af[mi][0], af[mi][1], af[mi][2], af[mi][3], addr);
            }
#pragma unroll
            for (int np = 0; np < 2; ++np) { // each x4 = two 8-col B frags
                const uint32_t addr = bBase + (uint32_t)(np * 16 * BSTR + kk * 8) * 4;
                LDSM_X4(bf[2 * np][0], bf[2 * np][1],
                        bf[2 * np + 1][0], bf[2 * np + 1][1], addr);
            }
#pragma unroll
            for (int mi = 0; mi < 4; ++mi)
#pragma unroll
                for (int ni = 0; ni < 4; ++ni)
                    mma_f16(acc[mi * 4 + ni], af[mi], bf[ni]);
        }
        __syncthreads();   // all warps done with slot before refill
    }

    // epilogue: c0,c1 at (row, col), c2,c3 at (row+8, col); col = 2*q4 (+1)
    const int rowB = blockIdx.y * 128 + warpM * 64 + quad;
    const int colB = blockIdx.x * 128 + warpN * 32 + q4 * 2;
#pragma unroll
    for (int mi = 0; mi < 4; ++mi) {
#pragma unroll
        for (int hf = 0; hf < 2; ++hf) {
            const int row = rowB + mi * 16 + hf * 8;
#pragma unroll
            for (int ni = 0; ni < 4; ++ni) {
                float v0 = acc[mi * 4 + ni][hf * 2];
                float v1 = acc[mi * 4 + ni][hf * 2 + 1];
                if (MODE >= 1) {
                    v0 += bias[colB + ni * 8];
                    v1 += bias[colB + ni * 8 + 1];
                }
                if (MODE == 2) {
                    __half* cp = (__half*)Cv + (size_t)row * N + colB + ni * 8;
                    __half2 h = __floats2half2_rn(gelu_tanh_f(v0), gelu_tanh_f(v1));
                    *(__half2*)cp = h;
                } else {
                    float* cp = (float*)Cv + (size_t)row * N + colB + ni * 8;
                    *(float2*)cp = make_float2(v0, v1);
                }
            }
        }
    }
}

// ---------------------------------------------------------------------------
// RoPE (in place) for q or k (fp32)
// ---------------------------------------------------------------------------
__global__ void rope_kernel(float* __restrict__ x, const float* __restrict__ cosA,
                            const float* __restrict__ sinA, int rowStride, int n)
{
    const int idx = blockIdx.x * blockDim.x + threadIdx.x;
    if (idx >= n) return;
    const int d = idx & 31;
    const int h = (idx >> 5) & 15;
    const int r = idx >> 9;
    const int s = r & 1023;
    float* p = x + (size_t)r * rowStride + h * HD_;
    const float x1 = p[d], x2 = p[d + 32];
    const float c1 = cosA[s * HD_ + d],      sv1 = sinA[s * HD_ + d];
    const float c2 = cosA[s * HD_ + d + 32], sv2 = sinA[s * HD_ + d + 32];
    p[d]      = x1 * c1 - x2 * sv1;
    p[d + 32] = x2 * c2 + x1 * sv2;
}

// ---------------------------------------------------------------------------
// Tensor-core flash attention (tf32 mma), group mask (attend iff gq != gk).
// Output fp16 (feeds Wo GEMM A). Internals unchanged from passing version.
// ---------------------------------------------------------------------------
constexpr int QS_OFF = 0;
constexpr int KT_OFF = 128 * 64;
constexpr int VT_OFF = 192 * 64;
constexpr int PS_OFF = 256 * 64;
constexpr int GK_OFF = 384 * 64;
constexpr int ATTN_SMEM_BYTES = (384 * 64 + 64) * 4;

__device__ __forceinline__ int ipos8(int k)
{
    return ((k & 3) << 1) | ((k & 4) >> 2);
}

__global__ __launch_bounds__(256, 2) void attn_mma_kernel(
    const float* __restrict__ Q, const float* __restrict__ KV,
    const int* __restrict__ gidx, __half* __restrict__ Out)
{
    extern __shared__ float smd[];
    float* Qs = smd + QS_OFF;
    float* Kt = smd + KT_OFF;
    float* Vt = smd + VT_OFF;
    float* Ps = smd + PS_OFF;
    int*  gks = (int*)(smd + GK_OFF);

    const int tid  = threadIdx.x;
    const int lane = tid & 31, w = tid >> 5;
    const int g = lane >> 2, t = lane & 3;
    const int bh = blockIdx.y, b = bh >> 4, h = bh & 15;
    const int q0 = blockIdx.x * 128;
    const int r0 = w * 16 + g;
    const int xr = (g & 3) << 3;

    for (int i = tid; i < 128 * 16; i += 256) {
        const int r = i >> 4, d4 = (i & 15) << 2;
        float4 v = *(const float4*)(Q + (size_t)(b * S_ + q0 + r) * D_ + h * HD_ + d4);
        const int xb = r * 64 + (((d4 & ~7) ^ ((r & 3) << 3)) + ((d4 & 4) ? 1 : 0));
        Qs[xb + 0] = tf32r(v.x * SCALE_);
        Qs[xb + 2] = tf32r(v.y * SCALE_);
        Qs[xb + 4] = tf32r(v.z * SCALE_);
        Qs[xb + 6] = tf32r(v.w * SCALE_);
    }
    const int gq0 = gidx[b * S_ + q0 + r0];
    const int gq1 = gidx[b * S_ + q0 + r0 + 8];

    float m0 = -1e30f, m1 = -1e30f, l0 = 0.f, l1 = 0.f;
    float o[8][4];
#pragma unroll
    for (int i = 0; i < 8; ++i)
#pragma unroll
        for (int j = 0; j < 4; ++j) o[i][j] = 0.f;

    const int p0 = ipos8(2 * t);
    const int p1 = ipos8(2 * t + 1);

    for (int kc = 0; kc < K_; kc += 64) {
        __syncthreads();

        for (int i = tid; i < 64 * 16; i += 256) {
            const int r = i >> 4, d4 = (i & 15) << 2;
            float4 v = *(const float4*)(KV + (size_t)(b * K_ + kc + r) * (2 * D_) + h * HD_ + d4);
            const int xb = r * 64 + (((d4 & ~7) ^ ((r & 3) << 3)) + ((d4 & 4) ? 1 : 0));
            Kt[xb + 0] = tf32r(v.x);
            Kt[xb + 2] = tf32r(v.y);
            Kt[xb + 4] = tf32r(v.z);
            Kt[xb + 6] = tf32r(v.w);
        }
        for (int i = tid; i < 64 * 16; i += 256) {
            const int r = i & 63, d4 = (i >> 6) << 2;
            float4 v = *(const float4*)(KV + (size_t)(b * K_ + kc + r) * (2 * D_) + D_ + h * HD_ + d4);
            const int kpos = (r & ~7) | ipos8(r & 7);
            Vt[(d4 + 0) * 64 + (kpos ^ (0 << 3))] = tf32r(v.x);
            Vt[(d4 + 1) * 64 + (kpos ^ (1 << 3))] = tf32r(v.y);
            Vt[(d4 + 2) * 64 + (kpos ^ (2 << 3))] = tf32r(v.z);
            Vt[(d4 + 3) * 64 + (kpos ^ (3 << 3))] = tf32r(v.w);
        }
        if (tid < 64) gks[tid] = gidx[b * K_ + kc + tid];
        __syncthreads();

        float s[8][4];
#pragma unroll
        for (int i = 0; i < 8; ++i)
#pragma unroll
            for (int j = 0; j < 4; ++j) s[i][j] = 0.f;

        const float* Aq0 = Qs + r0 * 64;
        const float* Aq1 = Qs + (r0 + 8) * 64;
#pragma unroll
        for (int ks = 0; ks < 8; ++ks) {
            const int col = ((8 * ks) ^ xr) + 2 * t;
            unsigned a[4];
            float2 lo = *(const float2*)(Aq0 + col);
            float2 hi = *(const float2*)(Aq1 + col);
            a[0] = __float_as_uint(lo.x); a[1] = __float_as_uint(hi.x);
            a[2] = __float_as_uint(lo.y); a[3] = __float_as_uint(hi.y);
#pragma unroll
            for (int nt = 0; nt < 8; ++nt) {
                float2 bb = *(const float2*)(Kt + (nt * 8 + g) * 64 + col);
                unsigned bf[2] = { __float_as_uint(bb.x), __float_as_uint(bb.y) };
                mma_tf32(s[nt], a, bf);
            }
        }

        float cm0 = -1e30f, cm1 = -1e30f;
#pragma unroll
        for (int nt = 0; nt < 8; ++nt) {
            const int k0i = gks[nt * 8 + 2 * t];
            const int k1i = gks[nt * 8 + 2 * t + 1];
            if (gq0 == k0i) s[nt][0] = -1000000000.0f;
            if (gq0 == k1i) s[nt][1] = -1000000000.0f;
            if (gq1 == k0i) s[nt][2] = -1000000000.0f;
            if (gq1 == k1i) s[nt][3] = -1000000000.0f;
            cm0 = fmaxf(cm0, fmaxf(s[nt][0], s[nt][1]));
            cm1 = fmaxf(cm1, fmaxf(s[nt][2], s[nt][3]));
        }
        cm0 = fmaxf(cm0, __shfl_xor_sync(~0u, cm0, 1));
        cm0 = fmaxf(cm0, __shfl_xor_sync(~0u, cm0, 2));
        cm1 = fmaxf(cm1, __shfl_xor_sync(~0u, cm1, 1));
        cm1 = fmaxf(cm1, __shfl_xor_sync(~0u, cm1, 2));

        const float mn0 = fmaxf(m0, cm0), mn1 = fmaxf(m1, cm1);
        const float f0 = __expf(m0 - mn0), f1 = __expf(m1 - mn1);
        m0 = mn0; m1 = mn1;

        float rs0 = 0.f, rs1 = 0.f;
#pragma unroll
        for (int nt = 0; nt < 8; ++nt) {
            s[nt][0] = __expf(s[nt][0] - mn0); rs0 += s[nt][0];
            s[nt][1] = __expf(s[nt][1] - mn0); rs0 += s[nt][1];
            s[nt][2] = __expf(s[nt][2] - mn1); rs1 += s[nt][2];
            s[nt][3] = __expf(s[nt][3] - mn1); rs1 += s[nt][3];
        }
        rs0 += __shfl_xor_sync(~0u, rs0, 1);
        rs0 += __shfl_xor_sync(~0u, rs0, 2);
        rs1 += __shfl_xor_sync(~0u, rs1, 1);
        rs1 += __shfl_xor_sync(~0u, rs1, 2);
        l0 = l0 * f0 + rs0;
        l1 = l1 * f1 + rs1;
#pragma unroll
        for (int nt = 0; nt < 8; ++nt) {
            o[nt][0] *= f0; o[nt][1] *= f0;
            o[nt][2] *= f1; o[nt][3] *= f1;
        }

        float* Pr0 = Ps + r0 * 64;
        float* Pr1 = Ps + (r0 + 8) * 64;
#pragma unroll
        for (int nt = 0; nt < 8; ++nt) {
            const int cbx = (nt * 8) ^ xr;
            Pr0[cbx + p0] = tf32r(s[nt][0]);
            Pr0[cbx + p1] = tf32r(s[nt][1]);
            Pr1[cbx + p0] = tf32r(s[nt][2]);
            Pr1[cbx + p1] = tf32r(s[nt][3]);
        }
        __syncwarp();

#pragma unroll
        for (int ks = 0; ks < 8; ++ks) {
            const int col = ((8 * ks) ^ xr) + 2 * t;
            unsigned a[4];
            float2 lo = *(const float2*)(Pr0 + col);
            float2 hi = *(const float2*)(Pr1 + col);
            a[0] = __float_as_uint(lo.x); a[1] = __float_as_uint(hi.x);
            a[2] = __float_as_uint(lo.y); a[3] = __float_as_uint(hi.y);
#pragma unroll
            for (int dt = 0; dt < 8; ++dt) {
                float2 bb = *(const float2*)(Vt + (dt * 8 + g) * 64 + col);
                unsigned bf[2] = { __float_as_uint(bb.x), __float_as_uint(bb.y) };
                mma_tf32(o[dt], a, bf);
            }
        }
        __syncwarp();
    }

    const float i0 = 1.0f / l0, i1 = 1.0f / l1;
    __half2* o0 = (__half2*)(Out + (size_t)(b * S_ + q0 + r0) * D_ + h * HD_) + t;
    __half2* o1 = (__half2*)(Out + (size_t)(b * S_ + q0 + r0 + 8) * D_ + h * HD_) + t;
#pragma unroll
    for (int dt = 0; dt < 8; ++dt) {
        o0[dt * 4] = __floats2half2_rn(o[dt][0] * i0, o[dt][1] * i0);
        o1[dt * 4] = __floats2half2_rn(o[dt][2] * i1, o[dt][3] * i1);
    }
}

// ---------------------------------------------------------------------------
// Gated residual: dst = qe ? g * go + xres : xres
// ---------------------------------------------------------------------------
__global__ void resid_kernel(const float* __restrict__ go, const float* __restrict__ xres,
                             const int* __restrict__ qe, float* __restrict__ dst, int gOff)
{
    const int i4 = blockIdx.x * blockDim.x + threadIdx.x;
    const int e   = i4 * 4;
    const int d   = e & (D_ - 1);
    const int row = e >> 10;
    const int b   = row >> 10;
    const float4 o  = *(const float4*)(go + e);
    const float4 xr = *(const float4*)(xres + e);
    float4 r;
    if (qe[row]) {
        const float4 g = *(const float4*)(g_mod + b * MODD_ + gOff + d);
        r.x = g.x * o.x + xr.x; r.y = g.y * o.y + xr.y;
        r.z = g.z * o.z + xr.z; r.w = g.w * o.w + xr.w;
    } else {
        r = xr;
    }
    *(float4*)(dst + e) = r;
}

// ---------------------------------------------------------------------------
// Host launcher
// ---------------------------------------------------------------------------
extern "C" void kernel_launch(void* const* d_in, const int* in_sizes, int n_in,
                              void* d_out, int out_size)
{
    const float* q_x    = (const float*)d_in[0];
    const float* kv_x   = (const float*)d_in[1];
    const float* t_cond = (const float*)d_in[2];
    const float* cos_q  = (const float*)d_in[3];
    const float* sin_q  = (const float*)d_in[4];
    const float* cos_k  = (const float*)d_in[5];
    const float* sin_k  = (const float*)d_in[6];
    const int*   gidx   = (const int*)d_in[7];
    const int*   qe     = (const int*)d_in[8];
    const float* qn_w   = (const float*)d_in[9];
    const float* kvn_w  = (const float*)d_in[10];
    const float* n2_w   = (const float*)d_in[11];
    const float* Wq     = (const float*)d_in[12];
    const float* Wkv    = (const float*)d_in[13];
    const float* Wo     = (const float*)d_in[14];
    const float* W1     = (const float*)d_in[15];
    const float* b1     = (const float*)d_in[16];
    const float* W2     = (const float*)d_in[17];
    const float* b2     = (const float*)d_in[18];
    const float* adaW   = (const float*)d_in[19];
    const float* adab   = (const float*)d_in[20];

    __half *p_qn, *p_kvn, *p_attn, *p_hn, *p_h1;
    float  *p_q, *p_kv, *p_o, *p_x1, *p_h2;
    uint32_t *p_wq, *p_wkv, *p_wo, *p_w1, *p_w2;
    cudaGetSymbolAddress((void**)&p_qn,   g_qn_h);
    cudaGetSymbolAddress((void**)&p_kvn,  g_kvn_h);
    cudaGetSymbolAddress((void**)&p_q,    g_q);
    cudaGetSymbolAddress((void**)&p_kv,   g_kv);
    cudaGetSymbolAddress((void**)&p_attn, g_attn_h);
    cudaGetSymbolAddress((void**)&p_o,    g_o);
    cudaGetSymbolAddress((void**)&p_x1,   g_x1);
    cudaGetSymbolAddress((void**)&p_hn,   g_hn_h);
    cudaGetSymbolAddress((void**)&p_h1,   g_h1_h);
    cudaGetSymbolAddress((void**)&p_h2,   g_h2);
    cudaGetSymbolAddress((void**)&p_wq,   g_wq_h);
    cudaGetSymbolAddress((void**)&p_wkv,  g_wkv_h);
    cudaGetSymbolAddress((void**)&p_wo,   g_wo_h);
    cudaGetSymbolAddress((void**)&p_w1,   g_w1_h);
    cudaGetSymbolAddress((void**)&p_w2,   g_w2_h);

    static bool attr_set = false;
    if (!attr_set) {
        cudaFuncSetAttribute(attn_mma_kernel,
                             cudaFuncAttributeMaxDynamicSharedMemorySize,
                             ATTN_SMEM_BYTES);
        cudaFuncSetAttribute(mma_gemm<0>,
                             cudaFuncAttributeMaxDynamicSharedMemorySize,
                             GEMM_SMEM_BYTES);
        cudaFuncSetAttribute(mma_gemm<1>,
                             cudaFuncAttributeMaxDynamicSharedMemorySize,
                             GEMM_SMEM_BYTES);
        cudaFuncSetAttribute(mma_gemm<2>,
                             cudaFuncAttributeMaxDynamicSharedMemorySize,
                             GEMM_SMEM_BYTES);
        attr_set = true;
    }

    const int M = B_ * S_;                   // 4096

    // 0. Pack weights to K-major fp16 k-pair words (transposed)
    conv_wt_kernel<<<dim3(D_ / 32,     D_ / 64),   256>>>(Wq,  p_wq,  D_,      D_);
    conv_wt_kernel<<<dim3(2 * D_ / 32, D_ / 64),   256>>>(Wkv, p_wkv, 2 * D_,  D_);
    conv_wt_kernel<<<dim3(D_ / 32,     D_ / 64),   256>>>(Wo,  p_wo,  D_,      D_);
    conv_wt_kernel<<<dim3(HID_ / 32,   D_ / 64),   256>>>(W1,  p_w1,  HID_,    D_);
    conv_wt_kernel<<<dim3(D_ / 32,     HID_ / 64), 256>>>(W2,  p_w2,  D_,      HID_);

    // 1. adaLN modulation
    mod_kernel<<<MODD_ / 256, 256>>>(t_cond, adaW, adab);

    // 2. LayerNorms (+ msa modulation for q) -> fp16
    ln_kernel<<<M, 256>>>(q_x,  qn_w,  p_qn,  0, D_, 1);
    ln_kernel<<<M, 256>>>(kv_x, kvn_w, p_kvn, 0, 0,  0);

    // 3. Projections (fp16 m16n8k16 mma + ldmatrix)
    mma_gemm<0><<<dim3(D_ / 128,      M / 128), 256, GEMM_SMEM_BYTES>>>(
        p_qn,  p_wq,  nullptr, p_q,  M, D_,      D_);
    mma_gemm<0><<<dim3(2 * D_ / 128,  M / 128), 256, GEMM_SMEM_BYTES>>>(
        p_kvn, p_wkv, nullptr, p_kv, M, 2 * D_,  D_);

    // 4. RoPE (q and k in place, fp32)
    const int nrope = B_ * 1024 * H_ * 32;   // 2M pairs
    rope_kernel<<<nrope / 256, 256>>>(p_q,  cos_q, sin_q, D_,     nrope);
    rope_kernel<<<nrope / 256, 256>>>(p_kv, cos_k, sin_k, 2 * D_, nrope);

    // 5. Attention (tf32 flash attention) -> fp16 output
    attn_mma_kernel<<<dim3(S_ / 128, B_ * H_), 256, ATTN_SMEM_BYTES>>>(
        p_q, p_kv, gidx, p_attn);

    // 6. Output projection + gated residual -> x_mid
    mma_gemm<0><<<dim3(D_ / 128, M / 128), 256, GEMM_SMEM_BYTES>>>(
        p_attn, p_wo, nullptr, p_o, M, D_, D_);
    resid_kernel<<<(M * D_ / 4) / 256, 256>>>(p_o, q_x, qe, p_x1, 2 * D_);

    // 7. MLP
    ln_kernel<<<M, 256>>>(p_x1, n2_w, p_hn, 3 * D_, 4 * D_, 1);
    mma_gemm<2><<<dim3(HID_ / 128, M / 128), 256, GEMM_SMEM_BYTES>>>(
        p_hn, p_w1, b1, p_h1, M, HID_, D_);
    mma_gemm<1><<<dim3(D_ / 128,   M / 128), 256, GEMM_SMEM_BYTES>>>(
        p_h1, p_w2, b2, p_h2, M, D_, HID_);

    // 8. Final gated residual -> output
    resid_kernel<<<(M * D_ / 4) / 256, 256>>>(p_h2, p_x1, qe, (float*)d_out, 5 * D_);
}

// round 14
// speedup vs baseline: 1.4166x; 1.4166x over previous
#include <cuda_runtime.h>
#include <cuda_fp16.h>
#include <math.h>
#include <stdint.h>

// ---------------------------------------------------------------------------
// Problem constants
// ---------------------------------------------------------------------------
constexpr int B_    = 4;
constexpr int S_    = 1024;
constexpr int K_    = 1024;
constexpr int D_    = 1024;
constexpr int H_    = 16;
constexpr int HD_   = 64;
constexpr int COND_ = 1024;
constexpr int HID_  = 4096;          // MR * D
constexpr int MODD_ = 6 * D_;        // 6144
constexpr float EPS_    = 1e-5f;
constexpr float SCALE_  = 0.125f;    // 1/sqrt(64)
constexpr float GELU_C_ = 0.7978845608028654f;

// ---------------------------------------------------------------------------
// Scratch (device globals: no allocation allowed)
// ---------------------------------------------------------------------------
__device__ float    g_mod [B_ * MODD_];
__device__ __half   g_qn_h  [B_ * S_ * D_];
__device__ __half   g_kvn_h [B_ * K_ * D_];
__device__ float    g_q   [B_ * S_ * D_];
__device__ float    g_kv  [B_ * K_ * 2 * D_];
__device__ __half   g_attn_h[B_ * S_ * D_];
__device__ float    g_o   [B_ * S_ * D_];
__device__ float    g_x1  [B_ * S_ * D_];
__device__ __half   g_hn_h  [B_ * S_ * D_];
__device__ __half   g_h1_h  [B_ * S_ * HID_];
__device__ float    g_h2  [B_ * S_ * D_];
// k-pair-packed fp16 weights: word (kp, n) = {W[2kp][n], W[2kp+1][n]}
__device__ uint32_t g_wq_h [(D_ / 2) * D_];
__device__ uint32_t g_wkv_h[(D_ / 2) * 2 * D_];
__device__ uint32_t g_wo_h [(D_ / 2) * D_];
__device__ uint32_t g_w1_h [(D_ / 2) * HID_];
__device__ uint32_t g_w2_h [(HID_ / 2) * D_];

// ---------------------------------------------------------------------------
// helpers
// ---------------------------------------------------------------------------
__device__ __forceinline__ uint32_t smem_u32(const void* p)
{
    uint32_t a;
    asm("{ .reg .u64 t; cvta.to.shared.u64 t, %1; cvt.u32.u64 %0, t; }"
        : "=r"(a) : "l"(p));
    return a;
}

__device__ __forceinline__ void cpasync16(uint32_t smaddr, const void* g)
{
    asm volatile("cp.async.cg.shared.global [%0], [%1], 16;"
                 :: "r"(smaddr), "l"(g));
}

__device__ __forceinline__ float gelu_tanh_f(float x)
{
    const float x3 = x * x * x;
    const float t  = tanhf(GELU_C_ * (x + 0.044715f * x3));
    return 0.5f * x * (1.0f + t);
}

__device__ __forceinline__ float tf32r(float x)
{
    float r;
    asm("cvt.rna.tf32.f32 %0, %1;" : "=f"(r) : "f"(x));
    return r;
}

// tf32 m16n8k8 (attention only)
__device__ __forceinline__ void mma_tf32(float* d, const unsigned* a, const unsigned* b)
{
    asm volatile(
        "mma.sync.aligned.m16n8k8.row.col.f32.tf32.tf32.f32 "
        "{%0,%1,%2,%3}, {%4,%5,%6,%7}, {%8,%9}, {%0,%1,%2,%3};\n"
        : "+f"(d[0]), "+f"(d[1]), "+f"(d[2]), "+f"(d[3])
        : "r"(a[0]), "r"(a[1]), "r"(a[2]), "r"(a[3]),
          "r"(b[0]), "r"(b[1]));
}

// fp16 m16n8k16 (GEMMs), fp32 accumulate
__device__ __forceinline__ void mma_f16(float* d, const unsigned* a, const unsigned* b)
{
    asm volatile(
        "mma.sync.aligned.m16n8k16.row.col.f32.f16.f16.f32 "
        "{%0,%1,%2,%3}, {%4,%5,%6,%7}, {%8,%9}, {%0,%1,%2,%3};\n"
        : "+f"(d[0]), "+f"(d[1]), "+f"(d[2]), "+f"(d[3])
        : "r"(a[0]), "r"(a[1]), "r"(a[2]), "r"(a[3]),
          "r"(b[0]), "r"(b[1]));
}

// ---------------------------------------------------------------------------
// Weight pack (vectorized): W[K][N] fp32 -> word[kp][n] = {W[2kp][n], W[2kp+1][n]}
// grid: (N/1024, K/2); each thread handles 4 n-values: float4 x2 in, uint4 out.
// ---------------------------------------------------------------------------
__global__ __launch_bounds__(256) void conv_w_kernel(
    const float* __restrict__ W, uint32_t* __restrict__ out, int N)
{
    const int n  = (blockIdx.x * 256 + threadIdx.x) * 4;
    const int kp = blockIdx.y;
    const float4 a = *(const float4*)(W + (size_t)(2 * kp) * N + n);
    const float4 b = *(const float4*)(W + (size_t)(2 * kp + 1) * N + n);
    __half2 h0 = __floats2half2_rn(a.x, b.x);
    __half2 h1 = __floats2half2_rn(a.y, b.y);
    __half2 h2 = __floats2half2_rn(a.z, b.z);
    __half2 h3 = __floats2half2_rn(a.w, b.w);
    uint4 u;
    u.x = *(const uint32_t*)&h0;
    u.y = *(const uint32_t*)&h1;
    u.z = *(const uint32_t*)&h2;
    u.w = *(const uint32_t*)&h3;
    *(uint4*)(out + (size_t)kp * N + n) = u;
}

// ---------------------------------------------------------------------------
// mod = t_cond @ adaW + adab   -> g_mod [B, 6144]
// ---------------------------------------------------------------------------
__global__ __launch_bounds__(256) void mod_kernel(
    const float* __restrict__ t, const float* __restrict__ W,
    const float* __restrict__ bias)
{
    __shared__ float ts[B_ * COND_];          // 16 KB
    const int j = blockIdx.x * 256 + threadIdx.x;
    for (int i = threadIdx.x; i < B_ * COND_; i += 256) ts[i] = t[i];
    __syncthreads();

    float acc[B_];
    const float bz = bias[j];
#pragma unroll
    for (int b = 0; b < B_; ++b) acc[b] = bz;

    for (int c = 0; c < COND_; ++c) {
        const float w = W[(size_t)c * MODD_ + j];
#pragma unroll
        for (int b = 0; b < B_; ++b) acc[b] += ts[b * COND_ + c] * w;
    }
#pragma unroll
    for (int b = 0; b < B_; ++b) g_mod[b * MODD_ + j] = acc[b];
}

// ---------------------------------------------------------------------------
// LayerNorm (+ optional adaLN modulation) -> fp16 output (feeds GEMM A)
// ---------------------------------------------------------------------------
__global__ __launch_bounds__(256) void ln_kernel(
    const float* __restrict__ x, const float* __restrict__ w,
    __half* __restrict__ out, int shOff, int scOff, int useMod)
{
    const int row = blockIdx.x;
    const int b   = row >> 10;
    const int t   = threadIdx.x;
    const float4 v = *((const float4*)(x + (size_t)row * D_) + t);

    float sum = v.x + v.y + v.z + v.w;
    float sq  = v.x*v.x + v.y*v.y + v.z*v.z + v.w*v.w;
#pragma unroll
    for (int o = 16; o; o >>= 1) {
        sum += __shfl_xor_sync(~0u, sum, o);
        sq  += __shfl_xor_sync(~0u, sq,  o);
    }
    __shared__ float s1[8], s2[8], st[2];
    const int wid = t >> 5, lane = t & 31;
    if (lane == 0) { s1[wid] = sum; s2[wid] = sq; }
    __syncthreads();
    if (t == 0) {
        float a = 0.f, c = 0.f;
#pragma unroll
        for (int i = 0; i < 8; ++i) { a += s1[i]; c += s2[i]; }
        const float mean = a * (1.0f / D_);
        const float var  = c * (1.0f / D_) - mean * mean;
        st[0] = mean; st[1] = rsqrtf(var + EPS_);
    }
    __syncthreads();
    const float mean = st[0], rstd = st[1];
    const int d = t * 4;
    const float4 w4 = *(const float4*)(w + d);
    float4 y;
    y.x = (v.x - mean) * rstd * w4.x;
    y.y = (v.y - mean) * rstd * w4.y;
    y.z = (v.z - mean) * rstd * w4.z;
    y.w = (v.w - mean) * rstd * w4.w;
    if (useMod) {
        const float* mb = g_mod + b * MODD_;
        const float4 sh = *(const float4*)(mb + shOff + d);
        const float4 sc = *(const float4*)(mb + scOff + d);
        y.x = y.x * (1.f + sc.x) + sh.x;
        y.y = y.y * (1.f + sc.y) + sh.y;
        y.z = y.z * (1.f + sc.z) + sh.z;
        y.w = y.w * (1.f + sc.w) + sh.w;
    }
    uint2 u;
    __half2 h0 = __floats2half2_rn(y.x, y.y);
    __half2 h1 = __floats2half2_rn(y.z, y.w);
    u.x = *(const uint32_t*)&h0;
    u.y = *(const uint32_t*)&h1;
    *((uint2*)(out + (size_t)row * D_) + t) = u;
}

// ---------------------------------------------------------------------------
// Fused gated residual + LayerNorm(+mod):
//   x1 = qe ? g_msa * go + xres : xres          (written fp32)
//   hn = LN(x1) * (1 + sc_mlp) + sh_mlp         (written fp16)
// One block per row; x1 stays in registers through the LN reduction.
// ---------------------------------------------------------------------------
__global__ __launch_bounds__(256) void resid_ln_kernel(
    const float* __restrict__ go, const float* __restrict__ xres,
    const int* __restrict__ qe, const float* __restrict__ w,
    float* __restrict__ x1out, __half* __restrict__ hnout,
    int gateOff, int shOff, int scOff)
{
    const int row = blockIdx.x;
    const int b   = row >> 10;
    const int t   = threadIdx.x;
    const int d   = t * 4;
    const float* mb = g_mod + b * MODD_;

    const float4 o  = *((const float4*)(go   + (size_t)row * D_) + t);
    const float4 xr = *((const float4*)(xres + (size_t)row * D_) + t);
    float4 x;
    if (qe[row]) {
        const float4 g = *(const float4*)(mb + gateOff + d);
        x.x = g.x * o.x + xr.x; x.y = g.y * o.y + xr.y;
        x.z = g.z * o.z + xr.z; x.w = g.w * o.w + xr.w;
    } else {
        x = xr;
    }
    *((float4*)(x1out + (size_t)row * D_) + t) = x;

    float sum = x.x + x.y + x.z + x.w;
    float sq  = x.x*x.x + x.y*x.y + x.z*x.z + x.w*x.w;
#pragma unroll
    for (int o2 = 16; o2; o2 >>= 1) {
        sum += __shfl_xor_sync(~0u, sum, o2);
        sq  += __shfl_xor_sync(~0u, sq,  o2);
    }
    __shared__ float s1[8], s2[8], st[2];
    const int wid = t >> 5, lane = t & 31;
    if (lane == 0) { s1[wid] = sum; s2[wid] = sq; }
    __syncthreads();
    if (t == 0) {
        float a = 0.f, c = 0.f;
#pragma unroll
        for (int i = 0; i < 8; ++i) { a += s1[i]; c += s2[i]; }
        const float mean = a * (1.0f / D_);
        const float var  = c * (1.0f / D_) - mean * mean;
        st[0] = mean; st[1] = rsqrtf(var + EPS_);
    }
    __syncthreads();
    const float mean = st[0], rstd = st[1];
    const float4 w4 = *(const float4*)(w + d);
    const float4 sh = *(const float4*)(mb + shOff + d);
    const float4 sc = *(const float4*)(mb + scOff + d);
    float4 y;
    y.x = ((x.x - mean) * rstd * w4.x) * (1.f + sc.x) + sh.x;
    y.y = ((x.y - mean) * rstd * w4.y) * (1.f + sc.y) + sh.y;
    y.z = ((x.z - mean) * rstd * w4.z) * (1.f + sc.z) + sh.z;
    y.w = ((x.w - mean) * rstd * w4.w) * (1.f + sc.w) + sh.w;
    uint2 u;
    __half2 h0 = __floats2half2_rn(y.x, y.y);
    __half2 h1 = __floats2half2_rn(y.z, y.w);
    u.x = *(const uint32_t*)&h0;
    u.y = *(const uint32_t*)&h1;
    *((uint2*)(hnout + (size_t)row * D_) + t) = u;
}

// ---------------------------------------------------------------------------
// fp16 mma GEMM: C[M,N] = A[M,K] @ B[K,N]
//   A: fp16 row-major; B: k-pair-packed half2 words [K/2][N].
//   128x128 tile, Ktile=32 halves, 3-stage cp.async, 8 warps (64x32),
//   m16n8k16, fp32 accum. v1's verified conflict-free bank layout (in words).
//   Single barrier per ktile (slot s rewritten only after iter-s+1 barrier).
// MODE: 0 = plain f32 out, 1 = +bias f32 out, 2 = gelu(+bias) fp16 out
// ---------------------------------------------------------------------------
constexpr int ASTR = 20;    // A smem row stride (words = half2): 16 k-words + 4 pad
constexpr int BSTR = 136;   // B smem kp-row stride (words): 128 n + 8 pad
constexpr int A_STAGE = 128 * ASTR;          // 2560 words
constexpr int B_STAGE = 16 * BSTR;           // 2176 words
constexpr int GEMM_SMEM_BYTES = (3 * A_STAGE + 3 * B_STAGE) * 4;   // 56832

template <int MODE>
__global__ __launch_bounds__(256, 2) void mma_gemm(
    const __half* __restrict__ A, const uint32_t* __restrict__ Bw,
    const float* __restrict__ bias, void* __restrict__ Cv,
    int M, int N, int Kd)
{
    extern __shared__ uint32_t dynw[];
    uint32_t* AsmW = dynw;                    // [3][A_STAGE]
    uint32_t* BsmW = dynw + 3 * A_STAGE;      // [3][B_STAGE]
    const uint32_t sA = smem_u32(AsmW);
    const uint32_t sB = smem_u32(BsmW);

    const int tid   = threadIdx.x;
    const int lane  = tid & 31, wid = tid >> 5;
    const int warpM = wid >> 2, warpN = wid & 3;     // 2 x 4 warps
    const int quad  = lane >> 2, q4 = lane & 3;

    // cp.async staging coords
    const int aRow = tid >> 1;               // 0..127
    const int bRow = tid >> 4;               // 0..15 (kp-rows)
    const int bNc  = (tid & 15) * 8;         // word offset within 128-word row

    const __half*   Ag = A  + (size_t)(blockIdx.y * 128 + aRow) * Kd + (tid & 1) * 16;
    const uint32_t* Bg = Bw + (size_t)bRow * N + blockIdx.x * 128 + bNc;
    const uint32_t aOff = (uint32_t)(aRow * ASTR + (tid & 1) * 8) * 4;
    const uint32_t bOff = (uint32_t)(bRow * BSTR + bNc) * 4;

    const int ktiles = Kd >> 5;              // 32 halves per tile

    auto issue = [&](int s) {
        const int slot = s % 3;
        const uint32_t da = sA + (uint32_t)slot * (A_STAGE * 4) + aOff;
        const __half* ag = Ag + (size_t)s * 32;
        cpasync16(da,      ag);
        cpasync16(da + 16, ag + 8);
        const uint32_t db = sB + (uint32_t)slot * (B_STAGE * 4) + bOff;
        const uint32_t* bg = Bg + (size_t)s * 16 * N;
        cpasync16(db,      bg);
        cpasync16(db + 16, bg + 4);
    };

    float acc[16][4];
#pragma unroll
    for (int i = 0; i < 16; ++i)
#pragma unroll
        for (int j = 0; j < 4; ++j) acc[i][j] = 0.f;

    issue(0);
    asm volatile("cp.async.commit_group;" ::: "memory");
    issue(1);
    asm volatile("cp.async.commit_group;" ::: "memory");

    for (int kt = 0; kt < ktiles; ++kt) {
        asm volatile("cp.async.wait_group 1;" ::: "memory");
        __syncthreads();   // stage kt ready; also fences slot (kt-1)%3 reads
                           // from the previous iteration before issue(kt+2)
                           // rewrites it at the NEXT iteration (safe: rewrite
                           // of slot s happens only after barrier of iter s+1)

        if (kt + 2 < ktiles) issue(kt + 2);
        asm volatile("cp.async.commit_group;" ::: "memory");

        const int slot = kt % 3;
        const uint32_t* Ab = AsmW + slot * A_STAGE + (warpM * 64 + quad) * ASTR + q4;
        const uint32_t* Bb = BsmW + slot * B_STAGE + q4 * BSTR + warpN * 32 + quad;

#pragma unroll
        for (int kk = 0; kk < 2; ++kk) {     // two k16 steps per 32-half tile
            unsigned af[4][4], bf[4][2];
#pragma unroll
            for (int mi = 0; mi < 4; ++mi) {
                const uint32_t* p = Ab + mi * (16 * ASTR) + kk * 8;
                af[mi][0] = p[0];
                af[mi][1] = p[8 * ASTR];
                af[mi][2] = p[4];
                af[mi][3] = p[8 * ASTR + 4];
            }
#pragma unroll
            for (int ni = 0; ni < 4; ++ni) {
                const uint32_t* p = Bb + kk * (8 * BSTR) + ni * 8;
                bf[ni][0] = p[0];
                bf[ni][1] = p[4 * BSTR];
            }
#pragma unroll
            for (int mi = 0; mi < 4; ++mi)
#pragma unroll
                for (int ni = 0; ni < 4; ++ni)
                    mma_f16(acc[mi * 4 + ni], af[mi], bf[ni]);
        }
    }

    // epilogue: c0,c1 at (row, col), c2,c3 at (row+8, col); col = 2*q4 (+1)
    const int rowB = blockIdx.y * 128 + warpM * 64 + quad;
    const int colB = blockIdx.x * 128 + warpN * 32 + q4 * 2;
#pragma unroll
    for (int mi = 0; mi < 4; ++mi) {
#pragma unroll
        for (int half = 0; half < 2; ++half) {
            const int row = rowB + mi * 16 + half * 8;
#pragma unroll
            for (int ni = 0; ni < 4; ++ni) {
                float v0 = acc[mi * 4 + ni][half * 2];
                float v1 = acc[mi * 4 + ni][half * 2 + 1];
                if (MODE >= 1) {
                    v0 += bias[colB + ni * 8];
                    v1 += bias[colB + ni * 8 + 1];
                }
                if (MODE == 2) {
                    __half* cp = (__half*)Cv + (size_t)row * N + colB + ni * 8;
                    __half2 h = __floats2half2_rn(gelu_tanh_f(v0), gelu_tanh_f(v1));
                    *(__half2*)cp = h;
                } else {
                    float* cp = (float*)Cv + (size_t)row * N + colB + ni * 8;
                    *(float2*)cp = make_float2(v0, v1);
                }
            }
        }
    }
}

// ---------------------------------------------------------------------------
// RoPE (in place) for q or k (fp32)
// ---------------------------------------------------------------------------
__global__ void rope_kernel(float* __restrict__ x, const float* __restrict__ cosA,
                            const float* __restrict__ sinA, int rowStride, int n)
{
    const int idx = blockIdx.x * blockDim.x + threadIdx.x;
    if (idx >= n) return;
    const int d = idx & 31;
    const int h = (idx >> 5) & 15;
    const int r = idx >> 9;
    const int s = r & 1023;
    float* p = x + (size_t)r * rowStride + h * HD_;
    const float x1 = p[d], x2 = p[d + 32];
    const float c1 = cosA[s * HD_ + d],      sv1 = sinA[s * HD_ + d];
    const float c2 = cosA[s * HD_ + d + 32], sv2 = sinA[s * HD_ + d + 32];
    p[d]      = x1 * c1 - x2 * sv1;
    p[d + 32] = x2 * c2 + x1 * sv2;
}

// ---------------------------------------------------------------------------
// Tensor-core flash attention (tf32 mma), group mask (attend iff gq != gk).
// Output fp16 (feeds Wo GEMM A). Internals unchanged from passing version.
// ---------------------------------------------------------------------------
constexpr int QS_OFF = 0;
constexpr int KT_OFF = 128 * 64;
constexpr int VT_OFF = 192 * 64;
constexpr int PS_OFF = 256 * 64;
constexpr int GK_OFF = 384 * 64;
constexpr int ATTN_SMEM_BYTES = (384 * 64 + 64) * 4;

__device__ __forceinline__ int ipos8(int k)
{
    return ((k & 3) << 1) | ((k & 4) >> 2);
}

__global__ __launch_bounds__(256, 2) void attn_mma_kernel(
    const float* __restrict__ Q, const float* __restrict__ KV,
    const int* __restrict__ gidx, __half* __restrict__ Out)
{
    extern __shared__ float smd[];
    float* Qs = smd + QS_OFF;
    float* Kt = smd + KT_OFF;
    float* Vt = smd + VT_OFF;
    float* Ps = smd + PS_OFF;
    int*  gks = (int*)(smd + GK_OFF);

    const int tid  = threadIdx.x;
    const int lane = tid & 31, w = tid >> 5;
    const int g = lane >> 2, t = lane & 3;
    const int bh = blockIdx.y, b = bh >> 4, h = bh & 15;
    const int q0 = blockIdx.x * 128;
    const int r0 = w * 16 + g;
    const int xr = (g & 3) << 3;

    for (int i = tid; i < 128 * 16; i += 256) {
        const int r = i >> 4, d4 = (i & 15) << 2;
        float4 v = *(const float4*)(Q + (size_t)(b * S_ + q0 + r) * D_ + h * HD_ + d4);
        const int xb = r * 64 + (((d4 & ~7) ^ ((r & 3) << 3)) + ((d4 & 4) ? 1 : 0));
        Qs[xb + 0] = tf32r(v.x * SCALE_);
        Qs[xb + 2] = tf32r(v.y * SCALE_);
        Qs[xb + 4] = tf32r(v.z * SCALE_);
        Qs[xb + 6] = tf32r(v.w * SCALE_);
    }
    const int gq0 = gidx[b * S_ + q0 + r0];
    const int gq1 = gidx[b * S_ + q0 + r0 + 8];

    float m0 = -1e30f, m1 = -1e30f, l0 = 0.f, l1 = 0.f;
    float o[8][4];
#pragma unroll
    for (int i = 0; i < 8; ++i)
#pragma unroll
        for (int j = 0; j < 4; ++j) o[i][j] = 0.f;

    const int p0 = ipos8(2 * t);
    const int p1 = ipos8(2 * t + 1);

    for (int kc = 0; kc < K_; kc += 64) {
        __syncthreads();

        for (int i = tid; i < 64 * 16; i += 256) {
            const int r = i >> 4, d4 = (i & 15) << 2;
            float4 v = *(const float4*)(KV + (size_t)(b * K_ + kc + r) * (2 * D_) + h * HD_ + d4);
            const int xb = r * 64 + (((d4 & ~7) ^ ((r & 3) << 3)) + ((d4 & 4) ? 1 : 0));
            Kt[xb + 0] = tf32r(v.x);
            Kt[xb + 2] = tf32r(v.y);
            Kt[xb + 4] = tf32r(v.z);
            Kt[xb + 6] = tf32r(v.w);
        }
        for (int i = tid; i < 64 * 16; i += 256) {
            const int r = i & 63, d4 = (i >> 6) << 2;
            float4 v = *(const float4*)(KV + (size_t)(b * K_ + kc + r) * (2 * D_) + D_ + h * HD_ + d4);
            const int kpos = (r & ~7) | ipos8(r & 7);
            Vt[(d4 + 0) * 64 + (kpos ^ (0 << 3))] = tf32r(v.x);
            Vt[(d4 + 1) * 64 + (kpos ^ (1 << 3))] = tf32r(v.y);
            Vt[(d4 + 2) * 64 + (kpos ^ (2 << 3))] = tf32r(v.z);
            Vt[(d4 + 3) * 64 + (kpos ^ (3 << 3))] = tf32r(v.w);
        }
        if (tid < 64) gks[tid] = gidx[b * K_ + kc + tid];
        __syncthreads();

        float s[8][4];
#pragma unroll
        for (int i = 0; i < 8; ++i)
#pragma unroll
            for (int j = 0; j < 4; ++j) s[i][j] = 0.f;

        const float* Aq0 = Qs + r0 * 64;
        const float* Aq1 = Qs + (r0 + 8) * 64;
#pragma unroll
        for (int ks = 0; ks < 8; ++ks) {
            const int col = ((8 * ks) ^ xr) + 2 * t;
            unsigned a[4];
            float2 lo = *(const float2*)(Aq0 + col);
            float2 hi = *(const float2*)(Aq1 + col);
            a[0] = __float_as_uint(lo.x); a[1] = __float_as_uint(hi.x);
            a[2] = __float_as_uint(lo.y); a[3] = __float_as_uint(hi.y);
#pragma unroll
            for (int nt = 0; nt < 8; ++nt) {
                float2 bb = *(const float2*)(Kt + (nt * 8 + g) * 64 + col);
                unsigned bf[2] = { __float_as_uint(bb.x), __float_as_uint(bb.y) };
                mma_tf32(s[nt], a, bf);
            }
        }

        float cm0 = -1e30f, cm1 = -1e30f;
#pragma unroll
        for (int nt = 0; nt < 8; ++nt) {
            const int k0i = gks[nt * 8 + 2 * t];
            const int k1i = gks[nt * 8 + 2 * t + 1];
            if (gq0 == k0i) s[nt][0] = -1000000000.0f;
            if (gq0 == k1i) s[nt][1] = -1000000000.0f;
            if (gq1 == k0i) s[nt][2] = -1000000000.0f;
            if (gq1 == k1i) s[nt][3] = -1000000000.0f;
            cm0 = fmaxf(cm0, fmaxf(s[nt][0], s[nt][1]));
            cm1 = fmaxf(cm1, fmaxf(s[nt][2], s[nt][3]));
        }
        cm0 = fmaxf(cm0, __shfl_xor_sync(~0u, cm0, 1));
        cm0 = fmaxf(cm0, __shfl_xor_sync(~0u, cm0, 2));
        cm1 = fmaxf(cm1, __shfl_xor_sync(~0u, cm1, 1));
        cm1 = fmaxf(cm1, __shfl_xor_sync(~0u, cm1, 2));

        const float mn0 = fmaxf(m0, cm0), mn1 = fmaxf(m1, cm1);
        const float f0 = __expf(m0 - mn0), f1 = __expf(m1 - mn1);
        m0 = mn0; m1 = mn1;

        float rs0 = 0.f, rs1 = 0.f;
#pragma unroll
        for (int nt = 0; nt < 8; ++nt) {
            s[nt][0] = __expf(s[nt][0] - mn0); rs0 += s[nt][0];
            s[nt][1] = __expf(s[nt][1] - mn0); rs0 += s[nt][1];
            s[nt][2] = __expf(s[nt][2] - mn1); rs1 += s[nt][2];
            s[nt][3] = __expf(s[nt][3] - mn1); rs1 += s[nt][3];
        }
        rs0 += __shfl_xor_sync(~0u, rs0, 1);
        rs0 += __shfl_xor_sync(~0u, rs0, 2);
        rs1 += __shfl_xor_sync(~0u, rs1, 1);
        rs1 += __shfl_xor_sync(~0u, rs1, 2);
        l0 = l0 * f0 + rs0;
        l1 = l1 * f1 + rs1;
#pragma unroll
        for (int nt = 0; nt < 8; ++nt) {
            o[nt][0] *= f0; o[nt][1] *= f0;
            o[nt][2] *= f1; o[nt][3] *= f1;
        }

        float* Pr0 = Ps + r0 * 64;
        float* Pr1 = Ps + (r0 + 8) * 64;
#pragma unroll
        for (int nt = 0; nt < 8; ++nt) {
            const int cbx = (nt * 8) ^ xr;
            Pr0[cbx + p0] = tf32r(s[nt][0]);
            Pr0[cbx + p1] = tf32r(s[nt][1]);
            Pr1[cbx + p0] = tf32r(s[nt][2]);
            Pr1[cbx + p1] = tf32r(s[nt][3]);
        }
        __syncwarp();

#pragma unroll
        for (int ks = 0; ks < 8; ++ks) {
            const int col = ((8 * ks) ^ xr) + 2 * t;
            unsigned a[4];
            float2 lo = *(const float2*)(Pr0 + col);
            float2 hi = *(const float2*)(Pr1 + col);
            a[0] = __float_as_uint(lo.x); a[1] = __float_as_uint(hi.x);
            a[2] = __float_as_uint(lo.y); a[3] = __float_as_uint(hi.y);
#pragma unroll
            for (int dt = 0; dt < 8; ++dt) {
                float2 bb = *(const float2*)(Vt + (dt * 8 + g) * 64 + col);
                unsigned bf[2] = { __float_as_uint(bb.x), __float_as_uint(bb.y) };
                mma_tf32(o[dt], a, bf);
            }
        }
        __syncwarp();
    }

    const float i0 = 1.0f / l0, i1 = 1.0f / l1;
    __half2* o0 = (__half2*)(Out + (size_t)(b * S_ + q0 + r0) * D_ + h * HD_) + t;
    __half2* o1 = (__half2*)(Out + (size_t)(b * S_ + q0 + r0 + 8) * D_ + h * HD_) + t;
#pragma unroll
    for (int dt = 0; dt < 8; ++dt) {
        o0[dt * 4] = __floats2half2_rn(o[dt][0] * i0, o[dt][1] * i0);
        o1[dt * 4] = __floats2half2_rn(o[dt][2] * i1, o[dt][3] * i1);
    }
}

// ---------------------------------------------------------------------------
// Gated residual: dst = qe ? g * go + xres : xres   (final output only)
// ---------------------------------------------------------------------------
__global__ void resid_kernel(const float* __restrict__ go, const float* __restrict__ xres,
                             const int* __restrict__ qe, float* __restrict__ dst, int gOff)
{
    const int i4 = blockIdx.x * blockDim.x + threadIdx.x;
    const int e   = i4 * 4;
    const int d   = e & (D_ - 1);
    const int row = e >> 10;
    const int b   = row >> 10;
    const float4 o  = *(const float4*)(go + e);
    const float4 xr = *(const float4*)(xres + e);
    float4 r;
    if (qe[row]) {
        const float4 g = *(const float4*)(g_mod + b * MODD_ + gOff + d);
        r.x = g.x * o.x + xr.x; r.y = g.y * o.y + xr.y;
        r.z = g.z * o.z + xr.z; r.w = g.w * o.w + xr.w;
    } else {
        r = xr;
    }
    *(float4*)(dst + e) = r;
}

// ---------------------------------------------------------------------------
// Host launcher
// ---------------------------------------------------------------------------
extern "C" void kernel_launch(void* const* d_in, const int* in_sizes, int n_in,
                              void* d_out, int out_size)
{
    const float* q_x    = (const float*)d_in[0];
    const float* kv_x   = (const float*)d_in[1];
    const float* t_cond = (const float*)d_in[2];
    const float* cos_q  = (const float*)d_in[3];
    const float* sin_q  = (const float*)d_in[4];
    const float* cos_k  = (const float*)d_in[5];
    const float* sin_k  = (const float*)d_in[6];
    const int*   gidx   = (const int*)d_in[7];
    const int*   qe     = (const int*)d_in[8];
    const float* qn_w   = (const float*)d_in[9];
    const float* kvn_w  = (const float*)d_in[10];
    const float* n2_w   = (const float*)d_in[11];
    const float* Wq     = (const float*)d_in[12];
    const float* Wkv    = (const float*)d_in[13];
    const float* Wo     = (const float*)d_in[14];
    const float* W1     = (const float*)d_in[15];
    const float* b1     = (const float*)d_in[16];
    const float* W2     = (const float*)d_in[17];
    const float* b2     = (const float*)d_in[18];
    const float* adaW   = (const float*)d_in[19];
    const float* adab   = (const float*)d_in[20];

    __half *p_qn, *p_kvn, *p_attn, *p_hn, *p_h1;
    float  *p_q, *p_kv, *p_o, *p_x1, *p_h2;
    uint32_t *p_wq, *p_wkv, *p_wo, *p_w1, *p_w2;
    cudaGetSymbolAddress((void**)&p_qn,   g_qn_h);
    cudaGetSymbolAddress((void**)&p_kvn,  g_kvn_h);
    cudaGetSymbolAddress((void**)&p_q,    g_q);
    cudaGetSymbolAddress((void**)&p_kv,   g_kv);
    cudaGetSymbolAddress((void**)&p_attn, g_attn_h);
    cudaGetSymbolAddress((void**)&p_o,    g_o);
    cudaGetSymbolAddress((void**)&p_x1,   g_x1);
    cudaGetSymbolAddress((void**)&p_hn,   g_hn_h);
    cudaGetSymbolAddress((void**)&p_h1,   g_h1_h);
    cudaGetSymbolAddress((void**)&p_h2,   g_h2);
    cudaGetSymbolAddress((void**)&p_wq,   g_wq_h);
    cudaGetSymbolAddress((void**)&p_wkv,  g_wkv_h);
    cudaGetSymbolAddress((void**)&p_wo,   g_wo_h);
    cudaGetSymbolAddress((void**)&p_w1,   g_w1_h);
    cudaGetSymbolAddress((void**)&p_w2,   g_w2_h);

    static bool attr_set = false;
    if (!attr_set) {
        cudaFuncSetAttribute(attn_mma_kernel,
                             cudaFuncAttributeMaxDynamicSharedMemorySize,
                             ATTN_SMEM_BYTES);
        cudaFuncSetAttribute(mma_gemm<0>,
                             cudaFuncAttributeMaxDynamicSharedMemorySize,
                             GEMM_SMEM_BYTES);
        cudaFuncSetAttribute(mma_gemm<1>,
                             cudaFuncAttributeMaxDynamicSharedMemorySize,
                             GEMM_SMEM_BYTES);
        cudaFuncSetAttribute(mma_gemm<2>,
                             cudaFuncAttributeMaxDynamicSharedMemorySize,
                             GEMM_SMEM_BYTES);
        attr_set = true;
    }

    const int M = B_ * S_;                   // 4096

    // 0. Pack weights to fp16 k-pair words (vectorized x4)
    conv_w_kernel<<<dim3(D_ / 1024,     D_ / 2),   256>>>(Wq,  p_wq,  D_);
    conv_w_kernel<<<dim3(2 * D_ / 1024, D_ / 2),   256>>>(Wkv, p_wkv, 2 * D_);
    conv_w_kernel<<<dim3(D_ / 1024,     D_ / 2),   256>>>(Wo,  p_wo,  D_);
    conv_w_kernel<<<dim3(HID_ / 1024,   D_ / 2),   256>>>(W1,  p_w1,  HID_);
    conv_w_kernel<<<dim3(D_ / 1024,     HID_ / 2), 256>>>(W2,  p_w2,  D_);

    // 1. adaLN modulation
    mod_kernel<<<MODD_ / 256, 256>>>(t_cond, adaW, adab);

    // 2. LayerNorms (+ msa modulation for q) -> fp16
    ln_kernel<<<M, 256>>>(q_x,  qn_w,  p_qn,  0, D_, 1);
    ln_kernel<<<M, 256>>>(kv_x, kvn_w, p_kvn, 0, 0,  0);

    // 3. Projections (fp16 m16n8k16 mma)
    mma_gemm<0><<<dim3(D_ / 128,      M / 128), 256, GEMM_SMEM_BYTES>>>(
        p_qn,  p_wq,  nullptr, p_q,  M, D_,      D_);
    mma_gemm<0><<<dim3(2 * D_ / 128,  M / 128), 256, GEMM_SMEM_BYTES>>>(
        p_kvn, p_wkv, nullptr, p_kv, M, 2 * D_,  D_);

    // 4. RoPE (q and k in place, fp32)
    const int nrope = B_ * 1024 * H_ * 32;   // 2M pairs
    rope_kernel<<<nrope / 256, 256>>>(p_q,  cos_q, sin_q, D_,     nrope);
    rope_kernel<<<nrope / 256, 256>>>(p_kv, cos_k, sin_k, 2 * D_, nrope);

    // 5. Attention (tf32 flash attention) -> fp16 output
    attn_mma_kernel<<<dim3(S_ / 128, B_ * H_), 256, ATTN_SMEM_BYTES>>>(
        p_q, p_kv, gidx, p_attn);

    // 6. Output projection + fused gated residual + LN2 -> x_mid (f32) + hn (fp16)
    mma_gemm<0><<<dim3(D_ / 128, M / 128), 256, GEMM_SMEM_BYTES>>>(
        p_attn, p_wo, nullptr, p_o, M, D_, D_);
    resid_ln_kernel<<<M, 256>>>(p_o, q_x, qe, n2_w, p_x1, p_hn,
                                2 * D_, 3 * D_, 4 * D_);

    // 7. MLP
    mma_gemm<2><<<dim3(HID_ / 128, M / 128), 256, GEMM_SMEM_BYTES>>>(
        p_hn, p_w1, b1, p_h1, M, HID_, D_);
    mma_gemm<1><<<dim3(D_ / 128,   M / 128), 256, GEMM_SMEM_BYTES>>>(
        p_h1, p_w2, b2, p_h2, M, D_, HID_);

    // 8. Final gated residual -> output
    resid_kernel<<<(M * D_ / 4) / 256, 256>>>(p_h2, p_x1, qe, (float*)d_out, 5 * D_);
}